// round 8
// baseline (speedup 1.0000x reference)
#include <cuda_runtime.h>
#include <cmath>

#define TOKS 4096          // B_SZ * L
#define DD   1024          // D
#define NN   16            // N
#define ROWF ((2*DD + 1) * NN)   // 32784 floats per token in output

// scratch (no cudaMalloc allowed)
__device__ float g_B[TOKS][NN];
__device__ float g_C[TOKS][NN];
__device__ float g_s[TOKS];
__device__ float g_R[DD * NN];        // 1 / A

__device__ __forceinline__ float softplus_f(float z) {
    // matches jax.nn.softplus: max(z,0) + log1p(exp(-|z|))
    return fmaxf(z, 0.f) + log1pf(__expf(-fabsf(z)));
}

// ---------------------------------------------------------------------------
// Phase 1: projections. One token per warp, ZERO smem — the 132 KB weight set
// lives in L1 (228 KB with no smem carveout) and is shared by all warps on an
// SM. 512 blocks x 256 threads spreads 4096 warps evenly over 152 SMs.
// Block 0 also builds the 1/A table.
// ---------------------------------------------------------------------------
__global__ __launch_bounds__(256) void proj_kernel(
    const float* __restrict__ x, const float* __restrict__ Wb,
    const float* __restrict__ Wc, const float* __restrict__ Wd,
    const float* __restrict__ A)
{
    if (blockIdx.x == 0) {           // one-time 1/A table
        for (int i = threadIdx.x; i < DD * NN; i += blockDim.x)
            g_R[i] = __frcp_rn(A[i]);
    }

    const int tok  = (blockIdx.x * blockDim.x + threadIdx.x) >> 5;  // 0..4095
    const int lane = threadIdx.x & 31;
    const float4* xr = (const float4*)(x + (size_t)tok * DD);
    const float4* wb4 = (const float4*)Wb;
    const float4* wc4 = (const float4*)Wc;
    const float4* wd4 = (const float4*)Wd;

    float acc[33];
#pragma unroll
    for (int j = 0; j < 33; j++) acc[j] = 0.f;

#pragma unroll
    for (int i = 0; i < 8; i++) {
        const int c = i * 32 + lane;         // float4 index 0..255
        float4 xv = __ldg(xr + c);
#pragma unroll
        for (int j = 0; j < 33; j++) {
            float4 w;
            if (j < 16)      w = __ldg(wb4 + j * 256 + c);
            else if (j < 32) w = __ldg(wc4 + (j - 16) * 256 + c);
            else             w = __ldg(wd4 + c);
            acc[j] = fmaf(xv.x, w.x, fmaf(xv.y, w.y, fmaf(xv.z, w.z, fmaf(xv.w, w.w, acc[j]))));
        }
    }

#pragma unroll
    for (int j = 0; j < 33; j++) {
#pragma unroll
        for (int o = 16; o > 0; o >>= 1)
            acc[j] += __shfl_xor_sync(0xffffffffu, acc[j], o);
    }

    if (lane == 0) {
#pragma unroll
        for (int j = 0; j < 16; j++) g_B[tok][j] = acc[j];
#pragma unroll
        for (int j = 0; j < 16; j++) g_C[tok][j] = acc[16 + j];
        g_s[tok] = acc[32];
    }
}

// ---------------------------------------------------------------------------
// Phase 2 (unchanged from round 7 — proven 96 us): expansion + 537 MB
// streaming stores. Per-token smem stage computes Delta = softplus once per d
// and stages the x row; hot loop stays lean. 3 CTAs/SM.
//   A_bar    = exp(Delta * A[d,n])
//   deltaB_x = (A_bar - 1) * R[d,n] * B[tok,n] * x[tok,d]   (Delta cancels)
// ---------------------------------------------------------------------------
__global__ __launch_bounds__(512, 3) void ssm_kernel(
    const float* __restrict__ x, const float* __restrict__ A,
    const float* __restrict__ dparam, float* __restrict__ out)
{
    __shared__ float sD[DD];   // Delta per d
    __shared__ float sX[DD];   // x row

    const int tid = threadIdx.x;
    const int q   = tid & 3;    // n-quad 0..3
    const int dof = tid >> 2;   // 0..127
    const float4* A4 = (const float4*)A;
    const float4* R4 = (const float4*)g_R;

    for (int tok = blockIdx.x; tok < TOKS; tok += gridDim.x) {
        const float s = g_s[tok];
        float4 Bq = *((const float4*)g_B[tok] + q);
        const float* xr = x + (size_t)tok * DD;
        float* ob = out + (size_t)tok * ROWF;

        // stage Delta (1 softplus per d) and the x row
#pragma unroll
        for (int h = 0; h < 2; h++) {
            int d = tid + h * 512;
            sD[d] = softplus_f(s + __ldg(dparam + d));
            sX[d] = __ldg(xr + d);
        }
        __syncthreads();

        if (tid < 4)
            __stcs((float4*)(ob + 2 * DD * NN) + tid,
                   *((const float4*)g_C[tok] + tid));

#pragma unroll
        for (int it = 0; it < 8; it++) {
            int d = dof + it * 128;
            float Delta = sD[d];
            float xd    = sX[d];
            float4 a = __ldg(A4 + d * 4 + q);
            float4 r = __ldg(R4 + d * 4 + q);
            float4 eo, bo;
#define COMP(f)                                                              \
            {                                                                \
                float dA = Delta * a.f;                                      \
                float e  = __expf(dA);                                       \
                float em1 = (fabsf(dA) < 0.015625f)                          \
                    ? dA * fmaf(dA, fmaf(dA, 0.16666667f, 0.5f), 1.f)        \
                    : (e - 1.f);                                             \
                eo.f = e;                                                    \
                bo.f = em1 * (r.f * (Bq.f * xd));                            \
            }
            COMP(x) COMP(y) COMP(z) COMP(w)
#undef COMP
            __stcs((float4*)ob + (size_t)d * 4 + q, eo);
            __stcs((float4*)ob + (size_t)DD * 4 + (size_t)d * 4 + q, bo);
        }
        __syncthreads();   // sD/sX reused next token
    }
}

// ---------------------------------------------------------------------------
extern "C" void kernel_launch(void* const* d_in, const int* in_sizes, int n_in,
                              void* d_out, int out_size)
{
    const float* x  = (const float*)d_in[0];
    const float* Wb = (const float*)d_in[1];
    const float* Wc = (const float*)d_in[2];
    const float* Wd = (const float*)d_in[3];
    const float* A  = (const float*)d_in[4];
    const float* dp = (const float*)d_in[5];
    float* out = (float*)d_out;

    // Phase 1: projections (+1/A table) — zero smem, 1 token/warp, all SMs
    proj_kernel<<<512, 256>>>(x, Wb, Wc, Wd, A);
    // Phase 2: 3 CTAs/SM, grid-strided tokens, softplus staged in smem
    ssm_kernel<<<456, 512>>>(x, A, dp, out);
}